// round 2
// baseline (speedup 1.0000x reference)
#include <cuda_runtime.h>
#include <math.h>

#define BB 4
#define C 64
#define C2 128
#define H 128
#define W 128
#define HW (H*W)
#define FIELD_N (BB*C*HW)
#define TILE_H 8
#define TILE_W 16
#define NPIX 128
#define NTHREADS 512
#define MAX_STEPS 50
#define DT_C 0.1f
#define THRESH_C 0.01

// smem layout offsets (floats)
#define OFF_W1 0            // 128*64
#define OFF_W2 8192         // 64*128
#define OFF_H  16384        // 128*128
#define OFF_FP 32768        // 64*128 packed f (GEMM operand)
#define OFF_F  40960        // 64*10*18 halo (depthwise)
#define OFF_DW 52480        // 64*9
#define OFF_B1 53056        // 128
#define OFF_B2 53184        // 64
#define OFF_DB 53248        // 64
#define OFF_RED 53312       // 16
#define SMEM_FLOATS 53328
#define SMEM_BYTES (SMEM_FLOATS * 4)   // ~213 KB

typedef unsigned long long ull;

__device__ __forceinline__ ull pack2(float lo, float hi) {
    ull r;
    asm("mov.b64 %0, {%1, %2};" : "=l"(r) : "f"(lo), "f"(hi));
    return r;
}
__device__ __forceinline__ void unpack2(ull v, float& lo, float& hi) {
    asm("mov.b64 {%0, %1}, %2;" : "=f"(lo), "=f"(hi) : "l"(v));
}
__device__ __forceinline__ void ffma2(ull& d, ull a, ull b, ull c) {
    asm("fma.rn.f32x2 %0, %1, %2, %3;" : "=l"(d) : "l"(a), "l"(b), "l"(c));
}

__device__ float g_buf0[FIELD_N];
__device__ float g_buf1[FIELD_N];
__device__ int    g_done;
__device__ int    g_steps;
__device__ int    g_cur;
__device__ double g_sum;

__global__ void afe_init_kernel(const float* __restrict__ field) {
    int tid = blockIdx.x * blockDim.x + threadIdx.x;
    if (tid == 0) { g_done = 0; g_steps = 0; g_cur = 0; g_sum = 0.0; }
    int stride = gridDim.x * blockDim.x;
    for (int i = tid; i < FIELD_N; i += stride) g_buf0[i] = field[i];
}

__global__ __launch_bounds__(NTHREADS, 1)
void afe_step_kernel(const float* __restrict__ dw, const float* __restrict__ db,
                     const float* __restrict__ w1, const float* __restrict__ b1,
                     const float* __restrict__ w2, const float* __restrict__ b2,
                     const float* __restrict__ dcoeff) {
    if (g_done) return;

    extern __shared__ float sm[];
    float* sw1 = sm + OFF_W1;   // [j*64 + c]
    float* sw2 = sm + OFF_W2;   // [c*128 + j]
    float* sh  = sm + OFF_H;    // [j*128 + p]
    float* sfp = sm + OFF_FP;   // [c*128 + p] packed
    float* sf  = sm + OFF_F;    // [c*180 + row*18 + col] halo
    float* sdw = sm + OFF_DW;
    float* sb1 = sm + OFF_B1;
    float* sb2 = sm + OFF_B2;
    float* sdb = sm + OFF_DB;
    float* sred = sm + OFF_RED;

    const float* fin  = g_cur ? g_buf1 : g_buf0;
    float*       fout = g_cur ? g_buf0 : g_buf1;

    const int b  = blockIdx.z;
    const int y0 = blockIdx.y * TILE_H;
    const int x0 = blockIdx.x * TILE_W;
    const int tid = threadIdx.x;
    const int g  = tid & 31;    // lane: owns pixels 4g..4g+3
    const int ws = tid >> 5;    // warp index 0..15

    // ---- load weights / biases ----
    for (int i = tid; i < C2 * C; i += NTHREADS) sw1[i] = w1[i];
    for (int i = tid; i < C * C2; i += NTHREADS) sw2[i] = w2[i];
    for (int i = tid; i < C * 9; i += NTHREADS) sdw[i] = dw[i];
    if (tid < C2) sb1[tid] = b1[tid];
    if (tid >= C2 && tid < C2 + C) sb2[tid - C2] = b2[tid - C2];
    if (tid >= C2 + C && tid < C2 + 2 * C) sdb[tid - C2 - C] = db[tid - C2 - C];

    // ---- halo tile (zero-pad SAME) ----
    for (int i = tid; i < C * 180; i += NTHREADS) {
        int c  = i / 180;
        int r  = (i % 180) / 18;
        int xx = i % 18;
        int y = y0 - 1 + r;
        int x = x0 - 1 + xx;
        float v = 0.0f;
        if (y >= 0 && y < H && x >= 0 && x < W)
            v = fin[((b * C + c) * H + y) * W + x];
        sf[i] = v;
    }
    // ---- packed interior tile for GEMM (direct from gmem, coalesced) ----
    for (int i = tid; i < C * NPIX; i += NTHREADS) {
        int c = i >> 7;
        int p = i & 127;
        int r = p >> 4, col = p & 15;
        sfp[i] = fin[((b * C + c) * H + (y0 + r)) * W + (x0 + col)];
    }
    __syncthreads();

    // ---- stage 1: h = gelu(W1 f + b1); thread: j=ws*8+ij, pixels 4g..4g+3 ----
    {
        const int jbase = ws * 8;
        ull acc[8][2];
        #pragma unroll
        for (int ij = 0; ij < 8; ij++) {
            float bv = sb1[jbase + ij];
            acc[ij][0] = pack2(bv, bv);
            acc[ij][1] = acc[ij][0];
        }
        #pragma unroll 4
        for (int c = 0; c < C; c += 2) {
            float4 a0 = *(const float4*)&sfp[c * NPIX + 4 * g];
            float4 a1 = *(const float4*)&sfp[(c + 1) * NPIX + 4 * g];
            ull f00 = pack2(a0.x, a0.y), f01 = pack2(a0.z, a0.w);
            ull f10 = pack2(a1.x, a1.y), f11 = pack2(a1.z, a1.w);
            #pragma unroll
            for (int ij = 0; ij < 8; ij++) {
                float2 wv = *(const float2*)&sw1[(jbase + ij) * C + c];
                ull w0 = pack2(wv.x, wv.x);
                ull w1d = pack2(wv.y, wv.y);
                ffma2(acc[ij][0], w0, f00, acc[ij][0]);
                ffma2(acc[ij][1], w0, f01, acc[ij][1]);
                ffma2(acc[ij][0], w1d, f10, acc[ij][0]);
                ffma2(acc[ij][1], w1d, f11, acc[ij][1]);
            }
        }
        #pragma unroll
        for (int ij = 0; ij < 8; ij++) {
            float x0v, x1v, x2v, x3v;
            unpack2(acc[ij][0], x0v, x1v);
            unpack2(acc[ij][1], x2v, x3v);
            float4 o;
            o.x = 0.5f * x0v * (1.0f + erff(x0v * 0.70710678118654752f));
            o.y = 0.5f * x1v * (1.0f + erff(x1v * 0.70710678118654752f));
            o.z = 0.5f * x2v * (1.0f + erff(x2v * 0.70710678118654752f));
            o.w = 0.5f * x3v * (1.0f + erff(x3v * 0.70710678118654752f));
            *(float4*)&sh[(jbase + ij) * NPIX + 4 * g] = o;
        }
    }
    __syncthreads();

    // ---- stage 2: react = W2 h; thread: c=ws*4+ic, pixels 4g..4g+3 ----
    const int cbase = ws * 4;
    ull acc2[4][2];
    #pragma unroll
    for (int ic = 0; ic < 4; ic++) { acc2[ic][0] = 0ULL; acc2[ic][1] = 0ULL; }

    #pragma unroll 4
    for (int j = 0; j < C2; j += 2) {
        float4 h0 = *(const float4*)&sh[j * NPIX + 4 * g];
        float4 h1 = *(const float4*)&sh[(j + 1) * NPIX + 4 * g];
        ull p00 = pack2(h0.x, h0.y), p01 = pack2(h0.z, h0.w);
        ull p10 = pack2(h1.x, h1.y), p11 = pack2(h1.z, h1.w);
        #pragma unroll
        for (int ic = 0; ic < 4; ic++) {
            float2 wv = *(const float2*)&sw2[(cbase + ic) * C2 + j];
            ull w0 = pack2(wv.x, wv.x);
            ull w1d = pack2(wv.y, wv.y);
            ffma2(acc2[ic][0], w0, p00, acc2[ic][0]);
            ffma2(acc2[ic][1], w0, p01, acc2[ic][1]);
            ffma2(acc2[ic][0], w1d, p10, acc2[ic][0]);
            ffma2(acc2[ic][1], w1d, p11, acc2[ic][1]);
        }
    }

    // ---- depthwise + epilogue; thread: 4 channels x 4 contiguous pixels ----
    const float dc = dcoeff[0];
    const int r   = (4 * g) >> 4;       // row within tile (4 px never cross rows)
    const int col = (4 * g) & 15;       // starting col
    float lsum = 0.0f;
    #pragma unroll
    for (int ic = 0; ic < 4; ic++) {
        const int c = cbase + ic;
        float wd[9];
        #pragma unroll
        for (int t = 0; t < 9; t++) wd[t] = sdw[c * 9 + t];
        const float bias2 = sb2[c];
        const float dbv = sdb[c];
        const float* base = sf + c * 180;
        float react[4];
        unpack2(acc2[ic][0], react[0], react[1]);
        unpack2(acc2[ic][1], react[2], react[3]);
        float4 ov;
        float* ovp = (float*)&ov;
        #pragma unroll
        for (int k = 0; k < 4; k++) {
            float s = 0.0f;
            #pragma unroll
            for (int dy = 0; dy < 3; dy++) {
                #pragma unroll
                for (int dx = 0; dx < 3; dx++)
                    s = fmaf(wd[dy * 3 + dx], base[(r + dy) * 18 + col + k + dx], s);
            }
            float deriv = dc * (s + dbv) + react[k] + bias2;
            float fold = base[(r + 1) * 18 + col + k + 1];
            float fnew = fmaf(DT_C, deriv, fold);
            lsum += fabsf(fnew - fold);
            ovp[k] = fnew;
        }
        *(float4*)&fout[((b * C + c) * H + (y0 + r)) * W + (x0 + col)] = ov;
    }

    // ---- block reduce |delta| ----
    #pragma unroll
    for (int off = 16; off > 0; off >>= 1)
        lsum += __shfl_xor_sync(0xFFFFFFFFu, lsum, off);
    if (g == 0) sred[ws] = lsum;
    __syncthreads();
    if (tid == 0) {
        float bs = 0.0f;
        #pragma unroll
        for (int i = 0; i < 16; i++) bs += sred[i];
        atomicAdd(&g_sum, (double)bs);
    }
}

__global__ void afe_finalize_kernel() {
    if (!g_done) {
        double mean = g_sum / (double)FIELD_N;
        g_steps += 1;
        if (mean < THRESH_C) g_done = 1;
        g_cur ^= 1;
    }
    g_sum = 0.0;
}

__global__ void afe_output_kernel(float* __restrict__ out, int out_size) {
    const float* f = g_cur ? g_buf1 : g_buf0;
    int tid = blockIdx.x * blockDim.x + threadIdx.x;
    int stride = gridDim.x * blockDim.x;
    float stepsf = (float)g_steps;
    for (int i = tid; i < out_size; i += stride)
        out[i] = (i < FIELD_N) ? f[i] : stepsf;
}

extern "C" void kernel_launch(void* const* d_in, const int* in_sizes, int n_in,
                              void* d_out, int out_size) {
    const float* field  = (const float*)d_in[0];
    const float* dw     = (const float*)d_in[1];
    const float* db     = (const float*)d_in[2];
    const float* w1     = (const float*)d_in[3];
    const float* b1     = (const float*)d_in[4];
    const float* w2     = (const float*)d_in[5];
    const float* b2     = (const float*)d_in[6];
    const float* dcoeff = (const float*)d_in[7];

    cudaFuncSetAttribute(afe_step_kernel,
                         cudaFuncAttributeMaxDynamicSharedMemorySize, SMEM_BYTES);

    afe_init_kernel<<<1024, 256>>>(field);

    dim3 grid(W / TILE_W, H / TILE_H, BB);  // (8, 16, 4) = 512 blocks
    for (int s = 0; s < MAX_STEPS; s++) {
        afe_step_kernel<<<grid, NTHREADS, SMEM_BYTES>>>(dw, db, w1, b1, w2, b2, dcoeff);
        afe_finalize_kernel<<<1, 1>>>();
    }

    afe_output_kernel<<<2048, 256>>>((float*)d_out, out_size);
}

// round 4
// speedup vs baseline: 1.6192x; 1.6192x over previous
#include <cuda_runtime.h>
#include <cuda_bf16.h>
#include <math.h>

#define BB 4
#define C 64
#define C2 128
#define H 128
#define W 128
#define HW (H*W)
#define FIELD_N (BB*C*HW)
#define TILE_H 8
#define TILE_W 16
#define NT 256
#define MAX_STEPS 50
#define DT_C 0.1f
#define THRESH_C 0.01

// row paddings (elements) for conflict-free fragment LDS
#define LDA 72     // A1 / W1 rows of 64 bf16, padded
#define LDB2 136   // W2 rows of 128 bf16, padded

// ---- smem byte offsets ----
#define SM_SF   0                       // 64*180*4 = 46080 fp32 halo
#define SM_A1H  46080                   // 128*72*2 = 18432
#define SM_A1L  64512
#define SM_W1H  82944
#define SM_W1L  101376
#define SM_W2H  119808                  // 64*136*2 = 17408
#define SM_W2L  137216
#define SM_B1   154624                  // 512
#define SM_B2   155136                  // 256
#define SM_DB   155392                  // 256
#define SM_DW   155648                  // 2304
#define SM_RED  157952                  // 32
#define SMEM_BYTES 158016

typedef unsigned u32;
typedef unsigned short u16;

__device__ __forceinline__ u32 pack_bf16x2(float lo, float hi) {
    __nv_bfloat162 t = __floats2bfloat162_rn(lo, hi);  // .x = lo half
    return *reinterpret_cast<u32*>(&t);
}

// D += A * B  (m16n8k16, bf16 in, f32 acc), C aliased to D
__device__ __forceinline__ void mma_bf16(float* d, const u32* a, u32 b0, u32 b1) {
    asm volatile(
        "mma.sync.aligned.m16n8k16.row.col.f32.bf16.bf16.f32 "
        "{%0,%1,%2,%3}, {%4,%5,%6,%7}, {%8,%9}, {%0,%1,%2,%3};"
        : "+f"(d[0]), "+f"(d[1]), "+f"(d[2]), "+f"(d[3])
        : "r"(a[0]), "r"(a[1]), "r"(a[2]), "r"(a[3]), "r"(b0), "r"(b1));
}

__device__ float g_buf0[FIELD_N];
__device__ float g_buf1[FIELD_N];
__device__ int    g_done;
__device__ int    g_steps;
__device__ int    g_cur;
__device__ double g_sum;
// bf16 hi/lo weight splits, natural layouts: w1 [j=128][c=64], w2 [c=64][j=128]
__device__ __align__(16) u16 g_w1h[8192];
__device__ __align__(16) u16 g_w1l[8192];
__device__ __align__(16) u16 g_w2h[8192];
__device__ __align__(16) u16 g_w2l[8192];

__global__ void afe_init_kernel(const float* __restrict__ field) {
    int tid = blockIdx.x * blockDim.x + threadIdx.x;
    if (tid == 0) { g_done = 0; g_steps = 0; g_cur = 0; g_sum = 0.0; }
    int stride = gridDim.x * blockDim.x;
    for (int i = tid; i < FIELD_N; i += stride) g_buf0[i] = field[i];
}

__global__ void afe_prep_weights(const float* __restrict__ w1, const float* __restrict__ w2) {
    int tid = blockIdx.x * blockDim.x + threadIdx.x;
    int stride = gridDim.x * blockDim.x;
    for (int i = tid; i < C2 * C; i += stride) {
        float v = w1[i];
        __nv_bfloat16 hb = __float2bfloat16_rn(v);
        __nv_bfloat16 lb = __float2bfloat16_rn(v - __bfloat162float(hb));
        g_w1h[i] = *reinterpret_cast<u16*>(&hb);
        g_w1l[i] = *reinterpret_cast<u16*>(&lb);
    }
    for (int i = tid; i < C * C2; i += stride) {
        float v = w2[i];
        __nv_bfloat16 hb = __float2bfloat16_rn(v);
        __nv_bfloat16 lb = __float2bfloat16_rn(v - __bfloat162float(hb));
        g_w2h[i] = *reinterpret_cast<u16*>(&hb);
        g_w2l[i] = *reinterpret_cast<u16*>(&lb);
    }
}

__global__ __launch_bounds__(NT, 1)
void afe_step_kernel(const float* __restrict__ dw, const float* __restrict__ db,
                     const float* __restrict__ b1, const float* __restrict__ b2,
                     const float* __restrict__ dcoeff) {
    if (g_done) return;

    extern __shared__ char smc[];
    float* sf  = (float*)(smc + SM_SF);
    u16* sA1h = (u16*)(smc + SM_A1H);
    u16* sA1l = (u16*)(smc + SM_A1L);
    u16* sW1h = (u16*)(smc + SM_W1H);
    u16* sW1l = (u16*)(smc + SM_W1L);
    u16* sW2h = (u16*)(smc + SM_W2H);
    u16* sW2l = (u16*)(smc + SM_W2L);
    float* sb1 = (float*)(smc + SM_B1);
    float* sb2 = (float*)(smc + SM_B2);
    float* sdb = (float*)(smc + SM_DB);
    float* sdw = (float*)(smc + SM_DW);
    float* sred = (float*)(smc + SM_RED);

    const float* fin  = g_cur ? g_buf1 : g_buf0;
    float*       fout = g_cur ? g_buf0 : g_buf1;

    const int b  = blockIdx.z;
    const int y0 = blockIdx.y * TILE_H;
    const int x0 = blockIdx.x * TILE_W;
    const int tid = threadIdx.x;
    const int wwid = tid >> 5;       // warp 0..7 -> tile row, m16 pixel tile
    const int lane = tid & 31;
    const int g2 = lane >> 2;        // group id 0..7
    const int t4 = lane & 3;         // thread in group 0..3

    // ---- stage weights into padded smem ----
    #pragma unroll
    for (int i = tid; i < C2 * C; i += NT) {
        int j = i >> 6, c = i & 63;
        sW1h[j * LDA + c] = g_w1h[i];
        sW1l[j * LDA + c] = g_w1l[i];
    }
    #pragma unroll
    for (int i = tid; i < C * C2; i += NT) {
        int c = i >> 7, j = i & 127;
        sW2h[c * LDB2 + j] = g_w2h[i];
        sW2l[c * LDB2 + j] = g_w2l[i];
    }
    if (tid < C2) sb1[tid] = b1[tid];
    if (tid < C)  { sb2[tid] = b2[tid]; sdb[tid] = db[tid]; }
    for (int i = tid; i < C * 9; i += NT) sdw[i] = dw[i];

    // ---- fp32 halo tile [64][10][18], zero-pad SAME ----
    for (int i = tid; i < C * 180; i += NT) {
        int c  = i / 180;
        int rr = (i % 180) / 18;
        int xx = i % 18;
        int y = y0 - 1 + rr;
        int x = x0 - 1 + xx;
        float v = 0.0f;
        if (y >= 0 && y < H && x >= 0 && x < W)
            v = fin[((b * C + c) * H + y) * W + x];
        sf[i] = v;
    }
    __syncthreads();

    // ---- A1 = f^T [pixel 0..127][c 0..63] bf16 hi/lo ----
    #pragma unroll
    for (int i = tid; i < C * 128; i += NT) {
        int c = i >> 7, p = i & 127;
        float v = sf[c * 180 + ((p >> 4) + 1) * 18 + (p & 15) + 1];
        __nv_bfloat16 hb = __float2bfloat16_rn(v);
        __nv_bfloat16 lb = __float2bfloat16_rn(v - __bfloat162float(hb));
        sA1h[p * LDA + c] = *reinterpret_cast<u16*>(&hb);
        sA1l[p * LDA + c] = *reinterpret_cast<u16*>(&lb);
    }
    __syncthreads();

    // ---- GEMM1: acc1[p(16 per warp)][j=128] = sum_c A1 * w1^T ----
    // A fragment rows: pixel = 16*wwid + g2 (+8); k chunks kc=0..3
    u32 ah[4][4], al[4][4];
    {
        const int r0 = (16 * wwid + g2) * LDA;
        const int r1 = (16 * wwid + g2 + 8) * LDA;
        #pragma unroll
        for (int kc = 0; kc < 4; kc++) {
            int k0 = 16 * kc + 2 * t4;
            ah[kc][0] = *(const u32*)&sA1h[r0 + k0];
            ah[kc][1] = *(const u32*)&sA1h[r1 + k0];
            ah[kc][2] = *(const u32*)&sA1h[r0 + k0 + 8];
            ah[kc][3] = *(const u32*)&sA1h[r1 + k0 + 8];
            al[kc][0] = *(const u32*)&sA1l[r0 + k0];
            al[kc][1] = *(const u32*)&sA1l[r1 + k0];
            al[kc][2] = *(const u32*)&sA1l[r0 + k0 + 8];
            al[kc][3] = *(const u32*)&sA1l[r1 + k0 + 8];
        }
    }

    float acc1[16][4];
    #pragma unroll
    for (int nt = 0; nt < 16; nt++)
        #pragma unroll
        for (int e = 0; e < 4; e++) acc1[nt][e] = 0.0f;

    #pragma unroll
    for (int nt = 0; nt < 16; nt++) {
        const int rb = (8 * nt + g2) * LDA;
        #pragma unroll
        for (int kc = 0; kc < 4; kc++) {
            int k0 = 16 * kc + 2 * t4;
            u32 bh0 = *(const u32*)&sW1h[rb + k0];
            u32 bh1 = *(const u32*)&sW1h[rb + k0 + 8];
            u32 bl0 = *(const u32*)&sW1l[rb + k0];
            u32 bl1 = *(const u32*)&sW1l[rb + k0 + 8];
            mma_bf16(acc1[nt], ah[kc], bh0, bh1);
            mma_bf16(acc1[nt], ah[kc], bl0, bl1);
            mma_bf16(acc1[nt], al[kc], bh0, bh1);
        }
    }

    // ---- gelu(acc1 + b1) -> GEMM2 A fragments in registers ----
    // D-frag (g,2t),(g,2t+1),(g+8,2t),(g+8,2t+1) of tile nt maps to
    // A-frag a0..a3 of k-chunk kc: a0,a1 from nt=2kc; a2,a3 from nt=2kc+1.
    u32 a2h[8][4], a2l[8][4];
    #pragma unroll
    for (int nt = 0; nt < 16; nt++) {
        float bias0 = sb1[8 * nt + 2 * t4];
        float bias1 = sb1[8 * nt + 2 * t4 + 1];
        float x0 = acc1[nt][0] + bias0;
        float x1 = acc1[nt][1] + bias1;
        float x2 = acc1[nt][2] + bias0;
        float x3 = acc1[nt][3] + bias1;
        float gl0 = 0.5f * x0 * (1.0f + erff(x0 * 0.70710678118654752f));
        float gl1 = 0.5f * x1 * (1.0f + erff(x1 * 0.70710678118654752f));
        float gl2 = 0.5f * x2 * (1.0f + erff(x2 * 0.70710678118654752f));
        float gl3 = 0.5f * x3 * (1.0f + erff(x3 * 0.70710678118654752f));
        __nv_bfloat16 h0 = __float2bfloat16_rn(gl0);
        __nv_bfloat16 h1 = __float2bfloat16_rn(gl1);
        __nv_bfloat16 h2 = __float2bfloat16_rn(gl2);
        __nv_bfloat16 h3 = __float2bfloat16_rn(gl3);
        int kc = nt >> 1;
        int q  = (nt & 1) << 1;   // 0 -> a0,a1 ; 1 -> a2,a3
        a2h[kc][q]     = pack_bf16x2(__bfloat162float(h0), __bfloat162float(h1));
        a2h[kc][q + 1] = pack_bf16x2(__bfloat162float(h2), __bfloat162float(h3));
        a2l[kc][q]     = pack_bf16x2(gl0 - __bfloat162float(h0), gl1 - __bfloat162float(h1));
        a2l[kc][q + 1] = pack_bf16x2(gl2 - __bfloat162float(h2), gl3 - __bfloat162float(h3));
    }

    // ---- GEMM2: acc2[p][c_out=64] = sum_j h * w2^T ----
    float acc2[8][4];
    #pragma unroll
    for (int nt = 0; nt < 8; nt++)
        #pragma unroll
        for (int e = 0; e < 4; e++) acc2[nt][e] = 0.0f;

    #pragma unroll
    for (int nt = 0; nt < 8; nt++) {
        const int rb = (8 * nt + g2) * LDB2;
        #pragma unroll
        for (int kc = 0; kc < 8; kc++) {
            int k0 = 16 * kc + 2 * t4;
            u32 bh0 = *(const u32*)&sW2h[rb + k0];
            u32 bh1 = *(const u32*)&sW2h[rb + k0 + 8];
            u32 bl0 = *(const u32*)&sW2l[rb + k0];
            u32 bl1 = *(const u32*)&sW2l[rb + k0 + 8];
            mma_bf16(acc2[nt], a2h[kc], bh0, bh1);
            mma_bf16(acc2[nt], a2h[kc], bl0, bl1);
            mma_bf16(acc2[nt], a2l[kc], bh0, bh1);
        }
    }

    // ---- epilogue: depthwise + Euler + |delta| ----
    // thread covers pixels (row=wwid, col=g2) and (row=wwid, col=g2+8),
    // channels c_out = 8*nt + 2*t4 + e
    const float dc = __ldg(dcoeff);
    float lsum = 0.0f;
    #pragma unroll
    for (int nt = 0; nt < 8; nt++) {
        #pragma unroll
        for (int e = 0; e < 2; e++) {
            const int c = 8 * nt + 2 * t4 + e;
            const float* base = sf + c * 180;
            const float wd0 = sdw[c * 9 + 0], wd1 = sdw[c * 9 + 1], wd2 = sdw[c * 9 + 2];
            const float wd3 = sdw[c * 9 + 3], wd4 = sdw[c * 9 + 4], wd5 = sdw[c * 9 + 5];
            const float wd6 = sdw[c * 9 + 6], wd7 = sdw[c * 9 + 7], wd8 = sdw[c * 9 + 8];
            const float bias2 = sb2[c];
            const float dbv = sdb[c];
            #pragma unroll
            for (int half = 0; half < 2; half++) {
                const int col = g2 + 8 * half;
                float s;
                s = wd0 * base[(wwid + 0) * 18 + col + 0];
                s = fmaf(wd1, base[(wwid + 0) * 18 + col + 1], s);
                s = fmaf(wd2, base[(wwid + 0) * 18 + col + 2], s);
                s = fmaf(wd3, base[(wwid + 1) * 18 + col + 0], s);
                s = fmaf(wd4, base[(wwid + 1) * 18 + col + 1], s);
                s = fmaf(wd5, base[(wwid + 1) * 18 + col + 2], s);
                s = fmaf(wd6, base[(wwid + 2) * 18 + col + 0], s);
                s = fmaf(wd7, base[(wwid + 2) * 18 + col + 1], s);
                s = fmaf(wd8, base[(wwid + 2) * 18 + col + 2], s);
                float react = acc2[nt][2 * half + e] + bias2;
                float deriv = dc * (s + dbv) + react;
                float fold = base[(wwid + 1) * 18 + col + 1];
                float fnew = fmaf(DT_C, deriv, fold);
                lsum += fabsf(fnew - fold);
                fout[((b * C + c) * H + (y0 + wwid)) * W + (x0 + col)] = fnew;
            }
        }
    }

    // ---- reduce |delta| ----
    #pragma unroll
    for (int off = 16; off > 0; off >>= 1)
        lsum += __shfl_xor_sync(0xFFFFFFFFu, lsum, off);
    if (lane == 0) sred[wwid] = lsum;
    __syncthreads();
    if (tid == 0) {
        float bs = 0.0f;
        #pragma unroll
        for (int i = 0; i < 8; i++) bs += sred[i];
        atomicAdd(&g_sum, (double)bs);
    }
}

__global__ void afe_finalize_kernel() {
    if (!g_done) {
        double mean = g_sum / (double)FIELD_N;
        g_steps += 1;
        if (mean < THRESH_C) g_done = 1;
        g_cur ^= 1;
    }
    g_sum = 0.0;
}

__global__ void afe_output_kernel(float* __restrict__ out, int out_size) {
    const float* f = g_cur ? g_buf1 : g_buf0;
    int tid = blockIdx.x * blockDim.x + threadIdx.x;
    int stride = gridDim.x * blockDim.x;
    float stepsf = (float)g_steps;
    for (int i = tid; i < out_size; i += stride)
        out[i] = (i < FIELD_N) ? f[i] : stepsf;
}

extern "C" void kernel_launch(void* const* d_in, const int* in_sizes, int n_in,
                              void* d_out, int out_size) {
    const float* field  = (const float*)d_in[0];
    const float* dw     = (const float*)d_in[1];
    const float* db     = (const float*)d_in[2];
    const float* w1     = (const float*)d_in[3];
    const float* b1     = (const float*)d_in[4];
    const float* w2     = (const float*)d_in[5];
    const float* b2     = (const float*)d_in[6];
    const float* dcoeff = (const float*)d_in[7];

    cudaFuncSetAttribute(afe_step_kernel,
                         cudaFuncAttributeMaxDynamicSharedMemorySize, SMEM_BYTES);

    afe_init_kernel<<<1024, 256>>>(field);
    afe_prep_weights<<<64, 256>>>(w1, w2);

    dim3 grid(W / TILE_W, H / TILE_H, BB);  // (8, 16, 4) = 512 CTAs
    for (int s = 0; s < MAX_STEPS; s++) {
        afe_step_kernel<<<grid, NT, SMEM_BYTES>>>(dw, db, b1, b2, dcoeff);
        afe_finalize_kernel<<<1, 1>>>();
    }

    afe_output_kernel<<<2048, 256>>>((float*)d_out, out_size);
}

// round 5
// speedup vs baseline: 2.2033x; 1.3607x over previous
#include <cuda_runtime.h>
#include <cuda_bf16.h>
#include <math.h>

#define BB 4
#define C 64
#define C2 128
#define H 128
#define W 128
#define HW (H*W)
#define FIELD_N (BB*C*HW)
#define TILE_H 8
#define TILE_W 16
#define NT 256
#define NBLK 512
#define MAX_STEPS 50
#define DT_C 0.1f
#define THRESH_C 0.01

// ---- smem byte offsets ----
#define SM_SF   0          // 64*180*4 = 46080 fp32 halo
#define SM_W1H  46080      // 16384 (128 rows x 32 words, XOR-swizzled)
#define SM_W1L  62464
#define SM_W2H  78848      // 16384 (64 rows x 64 words, XOR-swizzled)
#define SM_W2L  95232
#define SM_B1   111616     // 512
#define SM_B2   112128     // 256
#define SM_DB   112384     // 256
#define SM_DW   112640     // 2304
#define SM_RED  114944     // 32
#define SMEM_BYTES 114976

typedef unsigned u32;
typedef unsigned short u16;

__device__ __forceinline__ u32 pack_bf16x2(float lo, float hi) {
    __nv_bfloat162 t = __floats2bfloat162_rn(lo, hi);  // .x = lo half
    return *reinterpret_cast<u32*>(&t);
}

// D += A * B  (m16n8k16, bf16 in, f32 acc)
__device__ __forceinline__ void mma_bf16(float* d, const u32* a, u32 b0, u32 b1) {
    asm volatile(
        "mma.sync.aligned.m16n8k16.row.col.f32.bf16.bf16.f32 "
        "{%0,%1,%2,%3}, {%4,%5,%6,%7}, {%8,%9}, {%0,%1,%2,%3};"
        : "+f"(d[0]), "+f"(d[1]), "+f"(d[2]), "+f"(d[3])
        : "r"(a[0]), "r"(a[1]), "r"(a[2]), "r"(a[3]), "r"(b0), "r"(b1));
}

// XOR-swizzled weight word load: row of `roww` 32-bit words, logical word w
__device__ __forceinline__ u32 ldsw(const u16* s, int row, int w, int roww) {
    int phys = w ^ ((row & 7) << 2);
    return *(const u32*)&s[row * (roww * 2) + phys * 2];
}

__device__ float g_buf0[FIELD_N];
__device__ float g_buf1[FIELD_N];
__device__ int      g_done;
__device__ int      g_steps;
__device__ int      g_cur;
__device__ double   g_sum;
__device__ unsigned g_count;
// bf16 hi/lo weight splits, PRE-SWIZZLED to smem layout
__device__ __align__(16) u16 g_w1h[8192];
__device__ __align__(16) u16 g_w1l[8192];
__device__ __align__(16) u16 g_w2h[8192];
__device__ __align__(16) u16 g_w2l[8192];

__global__ void afe_init_kernel(const float* __restrict__ field) {
    int tid = blockIdx.x * blockDim.x + threadIdx.x;
    if (tid == 0) { g_done = 0; g_steps = 0; g_cur = 0; g_sum = 0.0; g_count = 0u; }
    int stride = gridDim.x * blockDim.x;
    for (int i = tid; i < FIELD_N; i += stride) g_buf0[i] = field[i];
}

__global__ void afe_prep_weights(const float* __restrict__ w1, const float* __restrict__ w2) {
    int tid = blockIdx.x * blockDim.x + threadIdx.x;
    int stride = gridDim.x * blockDim.x;
    // w1 [j=128][c=64]: word = c>>1, phys = word ^ ((j&7)<<2)
    for (int i = tid; i < C2 * C; i += stride) {
        int j = i >> 6, c = i & 63;
        float v = w1[i];
        __nv_bfloat16 hb = __float2bfloat16_rn(v);
        __nv_bfloat16 lb = __float2bfloat16_rn(v - __bfloat162float(hb));
        int off = j * 64 + (((c >> 1) ^ ((j & 7) << 2)) << 1) + (c & 1);
        g_w1h[off] = *reinterpret_cast<u16*>(&hb);
        g_w1l[off] = *reinterpret_cast<u16*>(&lb);
    }
    // w2 [c=64][j=128]: word = j>>1, phys = word ^ ((c&7)<<2)
    for (int i = tid; i < C * C2; i += stride) {
        int c = i >> 7, j = i & 127;
        float v = w2[i];
        __nv_bfloat16 hb = __float2bfloat16_rn(v);
        __nv_bfloat16 lb = __float2bfloat16_rn(v - __bfloat162float(hb));
        int off = c * 128 + (((j >> 1) ^ ((c & 7) << 2)) << 1) + (j & 1);
        g_w2h[off] = *reinterpret_cast<u16*>(&hb);
        g_w2l[off] = *reinterpret_cast<u16*>(&lb);
    }
}

__global__ __launch_bounds__(NT, 2)
void afe_step_kernel(const float* __restrict__ dw, const float* __restrict__ db,
                     const float* __restrict__ b1, const float* __restrict__ b2,
                     const float* __restrict__ dcoeff) {
    if (g_done) return;

    extern __shared__ char smc[];
    float* sf  = (float*)(smc + SM_SF);
    u16* sW1h = (u16*)(smc + SM_W1H);
    u16* sW1l = (u16*)(smc + SM_W1L);
    u16* sW2h = (u16*)(smc + SM_W2H);
    u16* sW2l = (u16*)(smc + SM_W2L);
    float* sb1 = (float*)(smc + SM_B1);
    float* sb2 = (float*)(smc + SM_B2);
    float* sdb = (float*)(smc + SM_DB);
    float* sdw = (float*)(smc + SM_DW);
    float* sred = (float*)(smc + SM_RED);

    const float* fin  = g_cur ? g_buf1 : g_buf0;
    float*       fout = g_cur ? g_buf0 : g_buf1;

    const int b  = blockIdx.z;
    const int y0 = blockIdx.y * TILE_H;
    const int x0 = blockIdx.x * TILE_W;
    const int tid = threadIdx.x;
    const int wwid = tid >> 5;
    const int lane = tid & 31;
    const int g2 = lane >> 2;
    const int t4 = lane & 3;

    // ---- stage weights (linear uint4 copies; pre-swizzled in gmem) ----
    {
        uint4* d0 = (uint4*)sW1h; const uint4* s0 = (const uint4*)g_w1h;
        uint4* d1 = (uint4*)sW1l; const uint4* s1 = (const uint4*)g_w1l;
        uint4* d2 = (uint4*)sW2h; const uint4* s2 = (const uint4*)g_w2h;
        uint4* d3 = (uint4*)sW2l; const uint4* s3 = (const uint4*)g_w2l;
        #pragma unroll
        for (int i = tid; i < 1024; i += NT) {
            d0[i] = s0[i]; d1[i] = s1[i]; d2[i] = s2[i]; d3[i] = s3[i];
        }
    }
    if (tid < C2) sb1[tid] = b1[tid];
    if (tid < C)  { sb2[tid] = b2[tid]; sdb[tid] = db[tid]; }
    for (int i = tid; i < C * 9; i += NT) sdw[i] = dw[i];

    // ---- fp32 halo tile [64][10][18], zero-pad SAME ----
    for (int i = tid; i < C * 180; i += NT) {
        int c  = i / 180;
        int rr = (i % 180) / 18;
        int xx = i % 18;
        int y = y0 - 1 + rr;
        int x = x0 - 1 + xx;
        float v = 0.0f;
        if (y >= 0 && y < H && x >= 0 && x < W)
            v = fin[((b * C + c) * H + y) * W + x];
        sf[i] = v;
    }
    __syncthreads();

    // ---- A1 fragments in registers straight from sf ----
    // pixel p0 = 16*wwid + g2 -> (row wwid, col g2); p1 = p0+8 -> col g2+8
    u32 ah[4][4], al[4][4];
    {
        const int pr = (wwid + 1) * 18 + 1;
        #pragma unroll
        for (int kc = 0; kc < 4; kc++) {
            #pragma unroll
            for (int q = 0; q < 2; q++) {
                int c = 16 * kc + 2 * t4 + 8 * q;
                float v00 = sf[c * 180 + pr + g2];
                float v01 = sf[(c + 1) * 180 + pr + g2];
                float v10 = sf[c * 180 + pr + g2 + 8];
                float v11 = sf[(c + 1) * 180 + pr + g2 + 8];
                __nv_bfloat16 h00 = __float2bfloat16_rn(v00);
                __nv_bfloat16 h01 = __float2bfloat16_rn(v01);
                __nv_bfloat16 h10 = __float2bfloat16_rn(v10);
                __nv_bfloat16 h11 = __float2bfloat16_rn(v11);
                ah[kc][2 * q]     = pack_bf16x2(__bfloat162float(h00), __bfloat162float(h01));
                ah[kc][2 * q + 1] = pack_bf16x2(__bfloat162float(h10), __bfloat162float(h11));
                al[kc][2 * q]     = pack_bf16x2(v00 - __bfloat162float(h00), v01 - __bfloat162float(h01));
                al[kc][2 * q + 1] = pack_bf16x2(v10 - __bfloat162float(h10), v11 - __bfloat162float(h11));
            }
        }
    }

    // ---- GEMM1 in two N-halves; gelu in registers -> GEMM2 A fragments ----
    u32 a2h[8][4], a2l[8][4];
    #pragma unroll
    for (int h = 0; h < 2; h++) {
        float acc[8][4];
        #pragma unroll
        for (int ntl = 0; ntl < 8; ntl++)
            #pragma unroll
            for (int e = 0; e < 4; e++) acc[ntl][e] = 0.0f;

        #pragma unroll
        for (int ntl = 0; ntl < 8; ntl++) {
            const int row = 8 * (8 * h + ntl) + g2;   // j row
            #pragma unroll
            for (int kc = 0; kc < 4; kc++) {
                u32 bh0 = ldsw(sW1h, row, 8 * kc + t4, 32);
                u32 bh1 = ldsw(sW1h, row, 8 * kc + t4 + 4, 32);
                u32 bl0 = ldsw(sW1l, row, 8 * kc + t4, 32);
                u32 bl1 = ldsw(sW1l, row, 8 * kc + t4 + 4, 32);
                mma_bf16(acc[ntl], ah[kc], bh0, bh1);
                mma_bf16(acc[ntl], ah[kc], bl0, bl1);
                mma_bf16(acc[ntl], al[kc], bh0, bh1);
            }
        }

        #pragma unroll
        for (int ntl = 0; ntl < 8; ntl++) {
            const int n = 8 * h + ntl;
            float bias0 = sb1[8 * n + 2 * t4];
            float bias1 = sb1[8 * n + 2 * t4 + 1];
            float x0 = acc[ntl][0] + bias0;
            float x1 = acc[ntl][1] + bias1;
            float x2 = acc[ntl][2] + bias0;
            float x3 = acc[ntl][3] + bias1;
            float gl0 = 0.5f * x0 * (1.0f + erff(x0 * 0.70710678118654752f));
            float gl1 = 0.5f * x1 * (1.0f + erff(x1 * 0.70710678118654752f));
            float gl2 = 0.5f * x2 * (1.0f + erff(x2 * 0.70710678118654752f));
            float gl3 = 0.5f * x3 * (1.0f + erff(x3 * 0.70710678118654752f));
            __nv_bfloat16 h0 = __float2bfloat16_rn(gl0);
            __nv_bfloat16 h1 = __float2bfloat16_rn(gl1);
            __nv_bfloat16 h2 = __float2bfloat16_rn(gl2);
            __nv_bfloat16 h3 = __float2bfloat16_rn(gl3);
            int kc2 = n >> 1;
            int q  = (n & 1) << 1;
            a2h[kc2][q]     = pack_bf16x2(__bfloat162float(h0), __bfloat162float(h1));
            a2h[kc2][q + 1] = pack_bf16x2(__bfloat162float(h2), __bfloat162float(h3));
            a2l[kc2][q]     = pack_bf16x2(gl0 - __bfloat162float(h0), gl1 - __bfloat162float(h1));
            a2l[kc2][q + 1] = pack_bf16x2(gl2 - __bfloat162float(h2), gl3 - __bfloat162float(h3));
        }
    }

    // ---- GEMM2: acc2[p][c=64] = sum_j h * w2^T ----
    float acc2[8][4];
    #pragma unroll
    for (int nt = 0; nt < 8; nt++)
        #pragma unroll
        for (int e = 0; e < 4; e++) acc2[nt][e] = 0.0f;

    #pragma unroll
    for (int nt = 0; nt < 8; nt++) {
        const int row = 8 * nt + g2;   // c row
        #pragma unroll
        for (int kc = 0; kc < 8; kc++) {
            u32 bh0 = ldsw(sW2h, row, 8 * kc + t4, 64);
            u32 bh1 = ldsw(sW2h, row, 8 * kc + t4 + 4, 64);
            u32 bl0 = ldsw(sW2l, row, 8 * kc + t4, 64);
            u32 bl1 = ldsw(sW2l, row, 8 * kc + t4 + 4, 64);
            mma_bf16(acc2[nt], a2h[kc], bh0, bh1);
            mma_bf16(acc2[nt], a2h[kc], bl0, bl1);
            mma_bf16(acc2[nt], a2l[kc], bh0, bh1);
        }
    }

    // ---- epilogue: depthwise + Euler + |delta| ----
    const float dc = __ldg(dcoeff);
    float lsum = 0.0f;
    #pragma unroll
    for (int nt = 0; nt < 8; nt++) {
        #pragma unroll
        for (int e = 0; e < 2; e++) {
            const int c = 8 * nt + 2 * t4 + e;
            const float* base = sf + c * 180;
            const float wd0 = sdw[c * 9 + 0], wd1 = sdw[c * 9 + 1], wd2 = sdw[c * 9 + 2];
            const float wd3 = sdw[c * 9 + 3], wd4 = sdw[c * 9 + 4], wd5 = sdw[c * 9 + 5];
            const float wd6 = sdw[c * 9 + 6], wd7 = sdw[c * 9 + 7], wd8 = sdw[c * 9 + 8];
            const float bias2 = sb2[c];
            const float dbv = sdb[c];
            #pragma unroll
            for (int half = 0; half < 2; half++) {
                const int col = g2 + 8 * half;
                float s;
                s = wd0 * base[(wwid + 0) * 18 + col + 0];
                s = fmaf(wd1, base[(wwid + 0) * 18 + col + 1], s);
                s = fmaf(wd2, base[(wwid + 0) * 18 + col + 2], s);
                s = fmaf(wd3, base[(wwid + 1) * 18 + col + 0], s);
                s = fmaf(wd4, base[(wwid + 1) * 18 + col + 1], s);
                s = fmaf(wd5, base[(wwid + 1) * 18 + col + 2], s);
                s = fmaf(wd6, base[(wwid + 2) * 18 + col + 0], s);
                s = fmaf(wd7, base[(wwid + 2) * 18 + col + 1], s);
                s = fmaf(wd8, base[(wwid + 2) * 18 + col + 2], s);
                float react = acc2[nt][2 * half + e] + bias2;
                float deriv = dc * (s + dbv) + react;
                float fold = base[(wwid + 1) * 18 + col + 1];
                float fnew = fmaf(DT_C, deriv, fold);
                lsum += fabsf(fnew - fold);
                fout[((b * C + c) * H + (y0 + wwid)) * W + (x0 + col)] = fnew;
            }
        }
    }

    // ---- reduce |delta|; last CTA finalizes the step ----
    #pragma unroll
    for (int off = 16; off > 0; off >>= 1)
        lsum += __shfl_xor_sync(0xFFFFFFFFu, lsum, off);
    if (lane == 0) sred[wwid] = lsum;
    __syncthreads();
    if (tid == 0) {
        float bs = 0.0f;
        #pragma unroll
        for (int i = 0; i < 8; i++) bs += sred[i];
        atomicAdd(&g_sum, (double)bs);
        __threadfence();
        unsigned prev = atomicAdd(&g_count, 1u);
        if (prev == NBLK - 1) {
            __threadfence();
            double mean = g_sum / (double)FIELD_N;
            g_steps += 1;
            if (mean < THRESH_C) g_done = 1;
            g_cur ^= 1;
            g_sum = 0.0;
            g_count = 0u;
            __threadfence();
        }
    }
}

__global__ void afe_output_kernel(float* __restrict__ out, int out_size) {
    const float* f = g_cur ? g_buf1 : g_buf0;
    int tid = blockIdx.x * blockDim.x + threadIdx.x;
    int stride = gridDim.x * blockDim.x;
    float stepsf = (float)g_steps;
    for (int i = tid; i < out_size; i += stride)
        out[i] = (i < FIELD_N) ? f[i] : stepsf;
}

extern "C" void kernel_launch(void* const* d_in, const int* in_sizes, int n_in,
                              void* d_out, int out_size) {
    const float* field  = (const float*)d_in[0];
    const float* dw     = (const float*)d_in[1];
    const float* db     = (const float*)d_in[2];
    const float* w1     = (const float*)d_in[3];
    const float* b1     = (const float*)d_in[4];
    const float* w2     = (const float*)d_in[5];
    const float* b2     = (const float*)d_in[6];
    const float* dcoeff = (const float*)d_in[7];

    cudaFuncSetAttribute(afe_step_kernel,
                         cudaFuncAttributeMaxDynamicSharedMemorySize, SMEM_BYTES);

    afe_init_kernel<<<1024, 256>>>(field);
    afe_prep_weights<<<64, 256>>>(w1, w2);

    dim3 grid(W / TILE_W, H / TILE_H, BB);  // (8, 16, 4) = 512 CTAs
    for (int s = 0; s < MAX_STEPS; s++) {
        afe_step_kernel<<<grid, NT, SMEM_BYTES>>>(dw, db, b1, b2, dcoeff);
    }

    afe_output_kernel<<<2048, 256>>>((float*)d_out, out_size);
}